// round 7
// baseline (speedup 1.0000x reference)
#include <cuda_runtime.h>
#include <cuda_fp16.h>
#include <cstdint>

#define BS    32
#define EMB   512
#define GL    256
#define WFLAT 36864
#define HIN   96
#define HOUT  94
#define NPIX  9216
#define XCLAMP (32u*64u*9216u - 4u)

typedef unsigned long long u64;
typedef unsigned int u32;

__device__ __align__(16) float  g_hdn_t[GL * BS];
// B in fp16 mma-fragment order: [s][kk][ks(4)][nt(8)][lane(32)][reg(2)][half(2)]
__device__ __align__(16) __half g_wB[BS * WFLAT];

// ---- helpers ----------------------------------------------------------------
__device__ __forceinline__ void fma2(u64& d, u64 a, u64 b) {
    asm("fma.rn.f32x2 %0, %1, %2, %0;" : "+l"(d) : "l"(a), "l"(b));
}
__device__ __forceinline__ void unpk2(u64 v, float& lo, float& hi) {
    asm("mov.b64 {%0, %1}, %2;" : "=f"(lo), "=f"(hi) : "l"(v));
}
__device__ __forceinline__ u32 smem_u32(const void* p) {
    u32 a; asm("{ .reg .u64 t; cvta.to.shared.u64 t, %1; cvt.u32.u64 %0, t; }" : "=r"(a) : "l"(p));
    return a;
}
__device__ __forceinline__ void cpa16(u32 dst, const void* src) {
    asm volatile("cp.async.cg.shared.global [%0], [%1], 16;" :: "r"(dst), "l"(src));
}
#define CPA_COMMIT() asm volatile("cp.async.commit_group;" ::: "memory")
#define CPA_WAIT(N)  asm volatile("cp.async.wait_group %0;" :: "n"(N) : "memory")

__device__ __forceinline__ void mma16(float* c, u32 a0, u32 a1, u32 a2, u32 a3,
                                      u32 b0, u32 b1) {
    asm("mma.sync.aligned.m16n8k16.row.col.f32.f16.f16.f32 "
        "{%0,%1,%2,%3}, {%4,%5,%6,%7}, {%8,%9}, {%0,%1,%2,%3};"
        : "+f"(c[0]), "+f"(c[1]), "+f"(c[2]), "+f"(c[3])
        : "r"(a0), "r"(a1), "r"(a2), "r"(a3), "r"(b0), "r"(b1));
}

// ---------------------------------------------------------------------------
__global__ __launch_bounds__(256) void hyper1(const float* __restrict__ emb,
                                              const float* __restrict__ w1w,
                                              const float* __restrict__ w1b) {
    __shared__ float red[8][33];
    const int tid = threadIdx.x;
    const int s = blockIdx.x >> 3, jg = blockIdx.x & 7;
    const int lane = tid & 31, slice = tid >> 5;
    const int j = jg * 32 + lane;
    const float4* wr = (const float4*)(w1w + (size_t)j * EMB + slice * 64);
    const float4* er = (const float4*)(emb + (size_t)s * EMB + slice * 64);
    float acc = 0.f;
#pragma unroll
    for (int k = 0; k < 16; k++) {
        float4 w = wr[k], e = er[k];
        acc += w.x * e.x + w.y * e.y + w.z * e.z + w.w * e.w;
    }
    red[slice][lane] = acc;
    __syncthreads();
    if (tid < 32) {
        float a = 0.f;
#pragma unroll
        for (int t = 0; t < 8; t++) a += red[t][tid];
        const int jj = jg * 32 + tid;
        a += w1b[jj];
        g_hdn_t[jj * BS + s] = a > 0.f ? a : 0.f;
    }
}

// ---------------------------------------------------------------------------
// hyper2: weight GEMM; epilogue writes fp16 values in m16n8k16 B-fragment order.
// ---------------------------------------------------------------------------
__global__ __launch_bounds__(128) void hyper2(const float* __restrict__ w2w,
                                              const float* __restrict__ w2b) {
    __shared__ float hdn_sm[GL * BS];
    __shared__ __align__(16) float2 w2td[64 * 33];

    const int tid = threadIdx.x;
    const int lane = tid & 31, sg = tid >> 5;
    const int r0 = blockIdx.x * 32;

#pragma unroll
    for (int it = 0; it < 16; it++)
        ((float4*)hdn_sm)[it * 128 + tid] = ((const float4*)g_hdn_t)[it * 128 + tid];

    u64 acc2[4];
#pragma unroll
    for (int i = 0; i < 4; i++) acc2[i] = 0ull;

    for (int kc = 0; kc < 4; kc++) {
        __syncthreads();
#pragma unroll
        for (int it = 0; it < 16; it++) {
            int idx = it * 128 + tid;
            int r = idx >> 6, kk = idx & 63;
            float v = w2w[(size_t)(r0 + r) * GL + kc * 64 + kk];
            w2td[kk * 33 + r] = make_float2(v, v);
        }
        __syncthreads();
#pragma unroll
        for (int k = 0; k < 64; k++) {
            const u64 wd = *(const u64*)&w2td[k * 33 + lane];
            const float* hb = &hdn_sm[(kc * 64 + k) * BS + sg * 8];
            fma2(acc2[0], wd, *(const u64*)&hb[0]);
            fma2(acc2[1], wd, *(const u64*)&hb[2]);
            fma2(acc2[2], wd, *(const u64*)&hb[4]);
            fma2(acc2[3], wd, *(const u64*)&hb[6]);
        }
    }

    const int row = r0 + lane;          // row = oc*576 + ic*9 + kk
    const int oc  = row / 576;
    const int rem = row - oc * 576;
    const int ic  = rem / 9;
    const int kk  = rem - ic * 9;
    const int ks = ic >> 4, kpos = ic & 15;
    const int reg = kpos >> 3, klo = kpos & 7;
    const int lanef = (oc & 7) * 4 + (klo >> 1);
    const int nt = oc >> 3, hsel = klo & 1;
    const int frag = ((((kk * 4 + ks) * 8 + nt) * 32 + lanef) * 2 + reg) * 2 + hsel;
    const float b = w2b[row];
#pragma unroll
    for (int pi = 0; pi < 4; pi++) {
        float lo, hi;
        unpk2(acc2[pi], lo, hi);
        const int s0 = sg * 8 + 2 * pi;
        g_wB[(size_t)s0 * WFLAT + frag]       = __float2half_rn(lo + b);
        g_wB[(size_t)(s0 + 1) * WFLAT + frag] = __float2half_rn(hi + b);
    }
}

// ---------------------------------------------------------------------------
// convk: fp16 mma.sync implicit GEMM. 256 px x 64 oc per CTA, one sample.
// A slab 32 icpairs x 450 px (half2, stride 456) staged once, MLP-parallel.
// B triple-buffered cp.async, ONE barrier per kk. grid=(36,32), block=256.
// ---------------------------------------------------------------------------
#define ASTR 456                               // half2 units per icpair row
#define SMA_BYTES (32 * ASTR * 4)              // 58368
#define SMEM_REQ  (SMA_BYTES + 3 * 8192)       // 82944

__global__ __launch_bounds__(256, 2) void convk(const float* __restrict__ x,
                                                float* __restrict__ out) {
    extern __shared__ char S[];
    half2*  sA = (half2*)S;
    __half* sB = (__half*)(S + SMA_BYTES);
    const u32 sBu = smem_u32(S) + SMA_BYTES;

    const int tid  = threadIdx.x;
    const int lane = tid & 31, wrp = tid >> 5;
    const int s    = blockIdx.y;
    const int p0   = blockIdx.x * 256;
    const u32 xs0  = (u32)s * (64u * NPIX);
    const __half* gB0 = g_wB + (size_t)s * 9 * 4096;

    // ---- prefetch B kk=0,1 first (rides under the A LDG burst) ----
#pragma unroll
    for (int i = 0; i < 2; i++)
        cpa16(sBu + (u32)((i * 256 + tid) * 16), (const char*)gB0 + (i * 256 + tid) * 16);
    CPA_COMMIT();
#pragma unroll
    for (int i = 0; i < 2; i++)
        cpa16(sBu + (u32)(8192 + (i * 256 + tid) * 16),
              (const char*)(gB0 + 4096) + (i * 256 + tid) * 16);
    CPA_COMMIT();

    // ---- stage A: 32 icpairs x 450 px (pad to 456), fully unrolled ----
#pragma unroll
    for (int ipl = 0; ipl < 4; ipl++) {
        const int ip  = wrp * 4 + ipl;
        const u32 r0b = xs0 + (u32)(2 * ip) * NPIX + (u32)p0;
#pragma unroll
        for (int c = 0; c < 4; c++) {
            const int px = c * 128 + lane * 4;
            if (px < 450) {
                u32 i0 = r0b + (u32)px;          if (i0 > XCLAMP) i0 = XCLAMP;
                u32 i1 = r0b + NPIX + (u32)px;   if (i1 > XCLAMP) i1 = XCLAMP;
                const float4 v0 = *(const float4*)(x + i0);
                const float4 v1 = *(const float4*)(x + i1);
                half2 h[4];
                h[0] = __floats2half2_rn(v0.x, v1.x);
                h[1] = __floats2half2_rn(v0.y, v1.y);
                h[2] = __floats2half2_rn(v0.z, v1.z);
                h[3] = __floats2half2_rn(v0.w, v1.w);
                *(uint4*)&sA[ip * ASTR + px] = *(const uint4*)h;
            }
        }
    }

    float acc[2][8][4];
#pragma unroll
    for (int mt = 0; mt < 2; mt++)
#pragma unroll
        for (int nt = 0; nt < 8; nt++)
#pragma unroll
            for (int r = 0; r < 4; r++) acc[mt][nt][r] = 0.f;

    const int pxb = wrp * 32 + (lane >> 2);

#pragma unroll 1
    for (int kk = 0; kk < 9; kk++) {
        if (kk < 8) { CPA_WAIT(1); } else { CPA_WAIT(0); }
        __syncthreads();   // buf kk ready for all; all warps done with buf (kk+2)%3

        if (kk <= 6) {     // prefetch kk+2
            const char* src = (const char*)(gB0 + (size_t)(kk + 2) * 4096);
            const u32 dst = sBu + (u32)(((kk + 2) % 3) * 8192);
#pragma unroll
            for (int i = 0; i < 2; i++)
                cpa16(dst + (u32)((i * 256 + tid) * 16), src + (i * 256 + tid) * 16);
            CPA_COMMIT();
        }

        const int off = (kk / 3) * 96 + (kk % 3);
        const __half* B = sB + (kk % 3) * 4096;

#pragma unroll
        for (int ks = 0; ks < 4; ks++) {
            u32 b0[8], b1[8];
#pragma unroll
            for (int nt = 0; nt < 8; nt++) {
                const uint2 bv = *(const uint2*)&B[((ks * 8 + nt) * 32 + lane) * 4];
                b0[nt] = bv.x; b1[nt] = bv.y;
            }
#pragma unroll
            for (int mt = 0; mt < 2; mt++) {
                const int a = (ks * 8 + (lane & 3)) * ASTR + pxb + mt * 16 + off;
                const u32 a0 = *(const u32*)&sA[a];
                const u32 a1 = *(const u32*)&sA[a + 8];
                const u32 a2 = *(const u32*)&sA[a + 4 * ASTR];
                const u32 a3 = *(const u32*)&sA[a + 4 * ASTR + 8];
#pragma unroll
                for (int nt = 0; nt < 8; nt++)
                    mma16(acc[mt][nt], a0, a1, a2, a3, b0[nt], b1[nt]);
            }
        }
    }

    // ---- epilogue: D[px][oc]; mask h,w >= 94 ----
    const int oc0 = (lane & 3) * 2;
#pragma unroll
    for (int mt = 0; mt < 2; mt++) {
#pragma unroll
        for (int hf = 0; hf < 2; hf++) {
            const int px = p0 + pxb + mt * 16 + hf * 8;
            const int h = px / 96, w = px - h * 96;
            if (h < HOUT && w < HOUT) {
                float* op = out + ((size_t)s * 64) * 8836 + h * 94 + w;
#pragma unroll
                for (int nt = 0; nt < 8; nt++) {
                    op[(nt * 8 + oc0 + 0) * 8836] = acc[mt][nt][hf * 2 + 0];
                    op[(nt * 8 + oc0 + 1) * 8836] = acc[mt][nt][hf * 2 + 1];
                }
            }
        }
    }
}

// ---------------------------------------------------------------------------
extern "C" void kernel_launch(void* const* d_in, const int* in_sizes, int n_in,
                              void* d_out, int out_size) {
    const float* emb = (const float*)d_in[0];
    const float* x   = (const float*)d_in[1];
    const float* w1w = (const float*)d_in[2];
    const float* w1b = (const float*)d_in[3];
    const float* w2w = (const float*)d_in[4];
    const float* w2b = (const float*)d_in[5];
    float* out = (float*)d_out;

    cudaFuncSetAttribute(convk, cudaFuncAttributeMaxDynamicSharedMemorySize, SMEM_REQ);

    hyper1<<<256, 256>>>(emb, w1w, w1b);
    hyper2<<<WFLAT / 32, 128>>>(w2w, w2b);
    convk<<<dim3(36, 32), 256, SMEM_REQ>>>(x, out);
}

// round 8
// speedup vs baseline: 1.0005x; 1.0005x over previous
#include <cuda_runtime.h>
#include <cuda_fp16.h>
#include <cstdint>

#define BS    32
#define EMB   512
#define GL    256
#define WFLAT 36864
#define HIN   96
#define HOUT  94
#define NPIX  9216
#define XCLAMP (32u*64u*9216u - 4u)

typedef unsigned long long u64;
typedef unsigned int u32;

__device__ __align__(16) float  g_hdn_t[GL * BS];
// B in fp16 mma-fragment order: [s][kk][ks(4)][nt(8)][lane(32)][reg(2)][half(2)]
__device__ __align__(16) __half g_wB[BS * WFLAT];

// ---- helpers ----------------------------------------------------------------
__device__ __forceinline__ void fma2(u64& d, u64 a, u64 b) {
    asm("fma.rn.f32x2 %0, %1, %2, %0;" : "+l"(d) : "l"(a), "l"(b));
}
__device__ __forceinline__ void unpk2(u64 v, float& lo, float& hi) {
    asm("mov.b64 {%0, %1}, %2;" : "=f"(lo), "=f"(hi) : "l"(v));
}
__device__ __forceinline__ u32 smem_u32(const void* p) {
    u32 a; asm("{ .reg .u64 t; cvta.to.shared.u64 t, %1; cvt.u32.u64 %0, t; }" : "=r"(a) : "l"(p));
    return a;
}
__device__ __forceinline__ void cpa16(u32 dst, const void* src) {
    asm volatile("cp.async.cg.shared.global [%0], [%1], 16;" :: "r"(dst), "l"(src));
}
#define CPA_COMMIT() asm volatile("cp.async.commit_group;" ::: "memory")
#define CPA_WAIT(N)  asm volatile("cp.async.wait_group %0;" :: "n"(N) : "memory")

__device__ __forceinline__ void mma16(float* c, u32 a0, u32 a1, u32 a2, u32 a3,
                                      u32 b0, u32 b1) {
    asm("mma.sync.aligned.m16n8k16.row.col.f32.f16.f16.f32 "
        "{%0,%1,%2,%3}, {%4,%5,%6,%7}, {%8,%9}, {%0,%1,%2,%3};"
        : "+f"(c[0]), "+f"(c[1]), "+f"(c[2]), "+f"(c[3])
        : "r"(a0), "r"(a1), "r"(a2), "r"(a3), "r"(b0), "r"(b1));
}

// ---------------------------------------------------------------------------
// hyper1: hdn_t[j][s] = relu(emb[s,:]·w1[j,:] + b1[j])
// grid = 256 (32 s x 8 jg), block 512 = 32 j-lanes x 16 k-slices
// ---------------------------------------------------------------------------
__global__ __launch_bounds__(512) void hyper1(const float* __restrict__ emb,
                                              const float* __restrict__ w1w,
                                              const float* __restrict__ w1b) {
    __shared__ float red[16][33];
    const int tid = threadIdx.x;
    const int s = blockIdx.x >> 3, jg = blockIdx.x & 7;
    const int lane = tid & 31, slice = tid >> 5;
    const int j = jg * 32 + lane;
    const float4* wr = (const float4*)(w1w + (size_t)j * EMB + slice * 32);
    const float4* er = (const float4*)(emb + (size_t)s * EMB + slice * 32);
    float acc = 0.f;
#pragma unroll
    for (int k = 0; k < 8; k++) {
        float4 w = wr[k], e = er[k];
        acc += w.x * e.x + w.y * e.y + w.z * e.z + w.w * e.w;
    }
    red[slice][lane] = acc;
    __syncthreads();
    if (tid < 32) {
        float a = 0.f;
#pragma unroll
        for (int t = 0; t < 16; t++) a += red[t][tid];
        const int jj = jg * 32 + tid;
        a += w1b[jj];
        g_hdn_t[jj * BS + s] = a > 0.f ? a : 0.f;
    }
}

// ---------------------------------------------------------------------------
// hyper2: weight GEMM; epilogue writes fp16 values in m16n8k16 B-fragment order.
// ---------------------------------------------------------------------------
__global__ __launch_bounds__(128) void hyper2(const float* __restrict__ w2w,
                                              const float* __restrict__ w2b) {
    __shared__ float hdn_sm[GL * BS];
    __shared__ __align__(16) float2 w2td[64 * 33];

    const int tid = threadIdx.x;
    const int lane = tid & 31, sg = tid >> 5;
    const int r0 = blockIdx.x * 32;

#pragma unroll
    for (int it = 0; it < 16; it++)
        ((float4*)hdn_sm)[it * 128 + tid] = ((const float4*)g_hdn_t)[it * 128 + tid];

    u64 acc2[4];
#pragma unroll
    for (int i = 0; i < 4; i++) acc2[i] = 0ull;

    for (int kc = 0; kc < 4; kc++) {
        __syncthreads();
#pragma unroll
        for (int it = 0; it < 16; it++) {
            int idx = it * 128 + tid;
            int r = idx >> 6, kk = idx & 63;
            float v = w2w[(size_t)(r0 + r) * GL + kc * 64 + kk];
            w2td[kk * 33 + r] = make_float2(v, v);
        }
        __syncthreads();
#pragma unroll
        for (int k = 0; k < 64; k++) {
            const u64 wd = *(const u64*)&w2td[k * 33 + lane];
            const float* hb = &hdn_sm[(kc * 64 + k) * BS + sg * 8];
            fma2(acc2[0], wd, *(const u64*)&hb[0]);
            fma2(acc2[1], wd, *(const u64*)&hb[2]);
            fma2(acc2[2], wd, *(const u64*)&hb[4]);
            fma2(acc2[3], wd, *(const u64*)&hb[6]);
        }
    }

    const int row = r0 + lane;          // row = oc*576 + ic*9 + kk
    const int oc  = row / 576;
    const int rem = row - oc * 576;
    const int ic  = rem / 9;
    const int kk  = rem - ic * 9;
    const int ks = ic >> 4, kpos = ic & 15;
    const int reg = kpos >> 3, klo = kpos & 7;
    const int lanef = (oc & 7) * 4 + (klo >> 1);
    const int nt = oc >> 3, hsel = klo & 1;
    const int frag = ((((kk * 4 + ks) * 8 + nt) * 32 + lanef) * 2 + reg) * 2 + hsel;
    const float b = w2b[row];
#pragma unroll
    for (int pi = 0; pi < 4; pi++) {
        float lo, hi;
        unpk2(acc2[pi], lo, hi);
        const int s0 = sg * 8 + 2 * pi;
        g_wB[(size_t)s0 * WFLAT + frag]       = __float2half_rn(lo + b);
        g_wB[(size_t)(s0 + 1) * WFLAT + frag] = __float2half_rn(hi + b);
    }
}

// ---------------------------------------------------------------------------
// convk: fp16 mma.sync implicit GEMM. 128 px x 64 oc per CTA, one sample.
// A slab 32 icpairs x 322 px (half2, stride 328) staged once, MLP-parallel.
// B triple-buffered cp.async, ONE barrier per kk. grid=(71,32), block=128.
// 3 CTAs/SM: staging/epilogue of one CTA hides under HMMA of the others.
// ---------------------------------------------------------------------------
#define ASTR 328                               // half2 units per icpair row
#define SMA_BYTES (32 * ASTR * 4)              // 41984
#define SMEM_REQ  (SMA_BYTES + 3 * 8192)       // 66560

__global__ __launch_bounds__(128, 3) void convk(const float* __restrict__ x,
                                                float* __restrict__ out) {
    extern __shared__ char S[];
    half2*  sA = (half2*)S;
    __half* sB = (__half*)(S + SMA_BYTES);
    const u32 sBu = smem_u32(S) + SMA_BYTES;

    const int tid  = threadIdx.x;
    const int lane = tid & 31, wrp = tid >> 5;
    const int s    = blockIdx.y;
    const int p0   = blockIdx.x * 128;
    const u32 xs0  = (u32)s * (64u * NPIX);
    const __half* gB0 = g_wB + (size_t)s * 9 * 4096;

    // ---- prefetch B kk=0,1 first (rides under the A LDG burst) ----
#pragma unroll
    for (int i = 0; i < 4; i++)
        cpa16(sBu + (u32)((i * 128 + tid) * 16), (const char*)gB0 + (i * 128 + tid) * 16);
    CPA_COMMIT();
#pragma unroll
    for (int i = 0; i < 4; i++)
        cpa16(sBu + (u32)(8192 + (i * 128 + tid) * 16),
              (const char*)(gB0 + 4096) + (i * 128 + tid) * 16);
    CPA_COMMIT();

    // ---- stage A: 32 icpairs x 322 px, fully unrolled (MLP ~24 LDG/thread) ----
#pragma unroll
    for (int ipl = 0; ipl < 8; ipl++) {
        const int ip  = wrp * 8 + ipl;
        const u32 r0b = xs0 + (u32)(2 * ip) * NPIX + (u32)p0;
#pragma unroll
        for (int c = 0; c < 3; c++) {
            const int px = c * 128 + lane * 4;
            u32 i0 = r0b + (u32)px;          if (i0 > XCLAMP) i0 = XCLAMP;
            u32 i1 = r0b + NPIX + (u32)px;   if (i1 > XCLAMP) i1 = XCLAMP;
            const float4 v0 = *(const float4*)(x + i0);
            const float4 v1 = *(const float4*)(x + i1);
            if (px < 326) {
                half2 h[4];
                h[0] = __floats2half2_rn(v0.x, v1.x);
                h[1] = __floats2half2_rn(v0.y, v1.y);
                h[2] = __floats2half2_rn(v0.z, v1.z);
                h[3] = __floats2half2_rn(v0.w, v1.w);
                *(uint4*)&sA[ip * ASTR + px] = *(const uint4*)h;
            }
        }
    }

    float acc[2][8][4];
#pragma unroll
    for (int mt = 0; mt < 2; mt++)
#pragma unroll
        for (int nt = 0; nt < 8; nt++)
#pragma unroll
            for (int r = 0; r < 4; r++) acc[mt][nt][r] = 0.f;

    const int pxb = wrp * 32 + (lane >> 2);

#pragma unroll 1
    for (int kk = 0; kk < 9; kk++) {
        if (kk < 8) { CPA_WAIT(1); } else { CPA_WAIT(0); }
        __syncthreads();   // buf kk ready; all warps done with buf (kk+2)%3

        if (kk <= 6) {     // prefetch kk+2
            const char* src = (const char*)(gB0 + (size_t)(kk + 2) * 4096);
            const u32 dst = sBu + (u32)(((kk + 2) % 3) * 8192);
#pragma unroll
            for (int i = 0; i < 4; i++)
                cpa16(dst + (u32)((i * 128 + tid) * 16), src + (i * 128 + tid) * 16);
            CPA_COMMIT();
        }

        const int off = (kk / 3) * 96 + (kk % 3);
        const __half* B = sB + (kk % 3) * 4096;

#pragma unroll
        for (int ks = 0; ks < 4; ks++) {
            u32 b0[8], b1[8];
#pragma unroll
            for (int nt = 0; nt < 8; nt++) {
                const uint2 bv = *(const uint2*)&B[((ks * 8 + nt) * 32 + lane) * 4];
                b0[nt] = bv.x; b1[nt] = bv.y;
            }
#pragma unroll
            for (int mt = 0; mt < 2; mt++) {
                const int a = (ks * 8 + (lane & 3)) * ASTR + pxb + mt * 16 + off;
                const u32 a0 = *(const u32*)&sA[a];
                const u32 a1 = *(const u32*)&sA[a + 8];
                const u32 a2 = *(const u32*)&sA[a + 4 * ASTR];
                const u32 a3 = *(const u32*)&sA[a + 4 * ASTR + 8];
#pragma unroll
                for (int nt = 0; nt < 8; nt++)
                    mma16(acc[mt][nt], a0, a1, a2, a3, b0[nt], b1[nt]);
            }
        }
    }

    // ---- epilogue: D[px][oc]; mask h,w >= 94 ----
    const int oc0 = (lane & 3) * 2;
#pragma unroll
    for (int mt = 0; mt < 2; mt++) {
#pragma unroll
        for (int hf = 0; hf < 2; hf++) {
            const int px = p0 + pxb + mt * 16 + hf * 8;
            const int h = px / 96, w = px - h * 96;
            if (h < HOUT && w < HOUT) {
                float* op = out + ((size_t)s * 64) * 8836 + h * 94 + w;
#pragma unroll
                for (int nt = 0; nt < 8; nt++) {
                    op[(nt * 8 + oc0 + 0) * 8836] = acc[mt][nt][hf * 2 + 0];
                    op[(nt * 8 + oc0 + 1) * 8836] = acc[mt][nt][hf * 2 + 1];
                }
            }
        }
    }
}

// ---------------------------------------------------------------------------
extern "C" void kernel_launch(void* const* d_in, const int* in_sizes, int n_in,
                              void* d_out, int out_size) {
    const float* emb = (const float*)d_in[0];
    const float* x   = (const float*)d_in[1];
    const float* w1w = (const float*)d_in[2];
    const float* w1b = (const float*)d_in[3];
    const float* w2w = (const float*)d_in[4];
    const float* w2b = (const float*)d_in[5];
    float* out = (float*)d_out;

    cudaFuncSetAttribute(convk, cudaFuncAttributeMaxDynamicSharedMemorySize, SMEM_REQ);

    hyper1<<<256, 512>>>(emb, w1w, w1b);
    hyper2<<<WFLAT / 32, 128>>>(w2w, w2b);
    // tile 71 (px >= 9088) is entirely h >= 94 -> dropped
    convk<<<dim3(71, 32), 128, SMEM_REQ>>>(x, out);
}

// round 9
// speedup vs baseline: 1.0377x; 1.0371x over previous
#include <cuda_runtime.h>
#include <cuda_fp16.h>
#include <cstdint>

#define BS    32
#define EMB   512
#define GL    256
#define WFLAT 36864
#define HIN   96
#define HOUT  94
#define NPIX  9216
#define XCLAMP (32u*64u*9216u - 4u)

typedef unsigned long long u64;
typedef unsigned int u32;

__device__ __align__(16) float  g_hdn_t[GL * BS];
// B fp16 fragment order: [s][kk][ks(4)][ntp(4)][lane(32)][ntl(2)][reg(2)][half(2)]
__device__ __align__(16) __half g_wB[BS * WFLAT];

// ---- helpers ----------------------------------------------------------------
__device__ __forceinline__ void fma2(u64& d, u64 a, u64 b) {
    asm("fma.rn.f32x2 %0, %1, %2, %0;" : "+l"(d) : "l"(a), "l"(b));
}
__device__ __forceinline__ void unpk2(u64 v, float& lo, float& hi) {
    asm("mov.b64 {%0, %1}, %2;" : "=f"(lo), "=f"(hi) : "l"(v));
}
__device__ __forceinline__ u32 smem_u32(const void* p) {
    u32 a; asm("{ .reg .u64 t; cvta.to.shared.u64 t, %1; cvt.u32.u64 %0, t; }" : "=r"(a) : "l"(p));
    return a;
}
__device__ __forceinline__ void cpa16(u32 dst, const void* src) {
    asm volatile("cp.async.cg.shared.global [%0], [%1], 16;" :: "r"(dst), "l"(src));
}
#define CPA_COMMIT() asm volatile("cp.async.commit_group;" ::: "memory")
#define CPA_WAIT(N)  asm volatile("cp.async.wait_group %0;" :: "n"(N) : "memory")

__device__ __forceinline__ void mma16(float* c, u32 a0, u32 a1, u32 a2, u32 a3,
                                      u32 b0, u32 b1) {
    asm("mma.sync.aligned.m16n8k16.row.col.f32.f16.f16.f32 "
        "{%0,%1,%2,%3}, {%4,%5,%6,%7}, {%8,%9}, {%0,%1,%2,%3};"
        : "+f"(c[0]), "+f"(c[1]), "+f"(c[2]), "+f"(c[3])
        : "r"(a0), "r"(a1), "r"(a2), "r"(a3), "r"(b0), "r"(b1));
}

// ---------------------------------------------------------------------------
// hyper1: hdn_t[j][s] = relu(emb[s,:]·w1[j,:] + b1[j])
// ---------------------------------------------------------------------------
__global__ __launch_bounds__(512) void hyper1(const float* __restrict__ emb,
                                              const float* __restrict__ w1w,
                                              const float* __restrict__ w1b) {
    __shared__ float red[16][33];
    const int tid = threadIdx.x;
    const int s = blockIdx.x >> 3, jg = blockIdx.x & 7;
    const int lane = tid & 31, slice = tid >> 5;
    const int j = jg * 32 + lane;
    const float4* wr = (const float4*)(w1w + (size_t)j * EMB + slice * 32);
    const float4* er = (const float4*)(emb + (size_t)s * EMB + slice * 32);
    float acc = 0.f;
#pragma unroll
    for (int k = 0; k < 8; k++) {
        float4 w = wr[k], e = er[k];
        acc += w.x * e.x + w.y * e.y + w.z * e.z + w.w * e.w;
    }
    red[slice][lane] = acc;
    __syncthreads();
    if (tid < 32) {
        float a = 0.f;
#pragma unroll
        for (int t = 0; t < 16; t++) a += red[t][tid];
        const int jj = jg * 32 + tid;
        a += w1b[jj];
        g_hdn_t[jj * BS + s] = a > 0.f ? a : 0.f;
    }
}

// ---------------------------------------------------------------------------
// hyper2: weight GEMM; float4 staging; epilogue writes fp16 in the LDS.128-
// friendly B-fragment order (ntl/reg/half packed per lane, 16B contiguous).
// ---------------------------------------------------------------------------
__global__ __launch_bounds__(128) void hyper2(const float* __restrict__ w2w,
                                              const float* __restrict__ w2b) {
    __shared__ float hdn_sm[GL * BS];
    __shared__ __align__(16) float2 w2td[64 * 33];

    const int tid = threadIdx.x;
    const int lane = tid & 31, sg = tid >> 5;
    const int r0 = blockIdx.x * 32;

#pragma unroll
    for (int it = 0; it < 16; it++)
        ((float4*)hdn_sm)[it * 128 + tid] = ((const float4*)g_hdn_t)[it * 128 + tid];

    u64 acc2[4];
#pragma unroll
    for (int i = 0; i < 4; i++) acc2[i] = 0ull;

    for (int kc = 0; kc < 4; kc++) {
        __syncthreads();
        // stage w2 tile: 32 rows x 64 kk via LDG.128 (4 per thread)
#pragma unroll
        for (int it = 0; it < 4; it++) {
            const int idx = it * 128 + tid;       // 0..511
            const int r = idx >> 4, c4 = idx & 15;
            const float4 v = *(const float4*)&w2w[(size_t)(r0 + r) * GL + kc * 64 + c4 * 4];
            w2td[(c4 * 4 + 0) * 33 + r] = make_float2(v.x, v.x);
            w2td[(c4 * 4 + 1) * 33 + r] = make_float2(v.y, v.y);
            w2td[(c4 * 4 + 2) * 33 + r] = make_float2(v.z, v.z);
            w2td[(c4 * 4 + 3) * 33 + r] = make_float2(v.w, v.w);
        }
        __syncthreads();
#pragma unroll
        for (int k = 0; k < 64; k++) {
            const u64 wd = *(const u64*)&w2td[k * 33 + lane];
            const float* hb = &hdn_sm[(kc * 64 + k) * BS + sg * 8];
            fma2(acc2[0], wd, *(const u64*)&hb[0]);
            fma2(acc2[1], wd, *(const u64*)&hb[2]);
            fma2(acc2[2], wd, *(const u64*)&hb[4]);
            fma2(acc2[3], wd, *(const u64*)&hb[6]);
        }
    }

    const int row = r0 + lane;          // row = oc*576 + ic*9 + kk
    const int oc  = row / 576;
    const int rem = row - oc * 576;
    const int ic  = rem / 9;
    const int kk  = rem - ic * 9;
    const int ks = ic >> 4, kpos = ic & 15;
    const int reg = kpos >> 3, klo = kpos & 7;
    const int lanef = (oc & 7) * 4 + (klo >> 1);
    const int hsel = klo & 1;
    const int nt = oc >> 3, ntp = nt >> 1, ntl = nt & 1;
    // half-index: [kk][ks][ntp][lane][ntl][reg][half]
    const int frag = (((kk * 4 + ks) * 4 + ntp) * 32 + lanef) * 8 + ntl * 4 + reg * 2 + hsel;
    const float b = w2b[row];
#pragma unroll
    for (int pi = 0; pi < 4; pi++) {
        float lo, hi;
        unpk2(acc2[pi], lo, hi);
        const int s0 = sg * 8 + 2 * pi;
        g_wB[(size_t)s0 * WFLAT + frag]       = __float2half_rn(lo + b);
        g_wB[(size_t)(s0 + 1) * WFLAT + frag] = __float2half_rn(hi + b);
    }
}

// ---------------------------------------------------------------------------
// convk: fp16 mma.sync implicit GEMM (R6 protocol). 128 px x 64 oc per CTA.
// A slab 32 icpairs x 322 px staged once; B double-buffered cp.async.
// B fragments loaded via LDS.128 (nt pairs). grid=(71,32), block=128.
// ---------------------------------------------------------------------------
#define ASTR 328                              // half2 units per icpair row
#define SMA_BYTES (32 * ASTR * 4)             // 41984
#define SMEM_REQ  (SMA_BYTES + 2 * 8192)      // 58368

__global__ __launch_bounds__(128) void convk(const float* __restrict__ x,
                                             float* __restrict__ out) {
    extern __shared__ char S[];
    half2*  sA = (half2*)S;
    __half* sB = (__half*)(S + SMA_BYTES);
    const u32 sBu = smem_u32(S) + SMA_BYTES;

    const int tid  = threadIdx.x;
    const int lane = tid & 31, wrp = tid >> 5;
    const int s    = blockIdx.y;
    const int p0   = blockIdx.x * 128;
    const u32 xs0  = (u32)s * (64u * NPIX);
    const __half* gB0 = g_wB + (size_t)s * 9 * 4096;

    // ---- prefetch B kk=0 (rides under the A LDG burst) ----
#pragma unroll
    for (int i = 0; i < 4; i++)
        cpa16(sBu + (u32)((i * 128 + tid) * 16), (const char*)gB0 + (i * 128 + tid) * 16);
    CPA_COMMIT();

    // ---- stage A: 32 icpairs x 322 px, fully unrolled (MLP ~24 LDG/thread) ----
#pragma unroll
    for (int ipl = 0; ipl < 8; ipl++) {
        const int ip  = wrp * 8 + ipl;
        const u32 r0b = xs0 + (u32)(2 * ip) * NPIX + (u32)p0;
#pragma unroll
        for (int c = 0; c < 3; c++) {
            const int px = c * 128 + lane * 4;
            u32 i0 = r0b + (u32)px;          if (i0 > XCLAMP) i0 = XCLAMP;
            u32 i1 = r0b + NPIX + (u32)px;   if (i1 > XCLAMP) i1 = XCLAMP;
            const float4 v0 = *(const float4*)(x + i0);
            const float4 v1 = *(const float4*)(x + i1);
            if (px < 326) {
                half2 h[4];
                h[0] = __floats2half2_rn(v0.x, v1.x);
                h[1] = __floats2half2_rn(v0.y, v1.y);
                h[2] = __floats2half2_rn(v0.z, v1.z);
                h[3] = __floats2half2_rn(v0.w, v1.w);
                *(uint4*)&sA[ip * ASTR + px] = *(const uint4*)h;
            }
        }
    }

    float acc[2][8][4];
#pragma unroll
    for (int mt = 0; mt < 2; mt++)
#pragma unroll
        for (int nt = 0; nt < 8; nt++)
#pragma unroll
            for (int r = 0; r < 4; r++) acc[mt][nt][r] = 0.f;

    const int pxb = wrp * 32 + (lane >> 2);

#pragma unroll 1
    for (int kk = 0; kk < 9; kk++) {
        if (kk < 8) {   // prefetch kk+1 into other buffer
            const char* src = (const char*)(gB0 + (size_t)(kk + 1) * 4096);
            const u32 dst = sBu + (u32)(((kk + 1) & 1) * 8192);
#pragma unroll
            for (int i = 0; i < 4; i++)
                cpa16(dst + (u32)((i * 128 + tid) * 16), src + (i * 128 + tid) * 16);
            CPA_COMMIT();
            CPA_WAIT(1);
        } else {
            CPA_WAIT(0);
        }
        __syncthreads();

        const int off = (kk / 3) * 96 + (kk % 3);
        const __half* B = sB + (kk & 1) * 4096;

#pragma unroll
        for (int ks = 0; ks < 4; ks++) {
            u32 b0[8], b1[8];
#pragma unroll
            for (int ntp = 0; ntp < 4; ntp++) {
                const uint4 bv = *(const uint4*)&B[((ks * 4 + ntp) * 32 + lane) * 8];
                b0[2 * ntp + 0] = bv.x; b1[2 * ntp + 0] = bv.y;
                b0[2 * ntp + 1] = bv.z; b1[2 * ntp + 1] = bv.w;
            }
#pragma unroll
            for (int mt = 0; mt < 2; mt++) {
                const int a = (ks * 8 + (lane & 3)) * ASTR + pxb + mt * 16 + off;
                const u32 a0 = *(const u32*)&sA[a];
                const u32 a1 = *(const u32*)&sA[a + 8];
                const u32 a2 = *(const u32*)&sA[a + 4 * ASTR];
                const u32 a3 = *(const u32*)&sA[a + 4 * ASTR + 8];
#pragma unroll
                for (int nt = 0; nt < 8; nt++)
                    mma16(acc[mt][nt], a0, a1, a2, a3, b0[nt], b1[nt]);
            }
        }
        __syncthreads();
    }

    // ---- epilogue: D[px][oc]; mask h,w >= 94 ----
    const int oc0 = (lane & 3) * 2;
#pragma unroll
    for (int mt = 0; mt < 2; mt++) {
#pragma unroll
        for (int hf = 0; hf < 2; hf++) {
            const int px = p0 + pxb + mt * 16 + hf * 8;
            const int h = px / 96, w = px - h * 96;
            if (h < HOUT && w < HOUT) {
                float* op = out + ((size_t)s * 64) * 8836 + h * 94 + w;
#pragma unroll
                for (int nt = 0; nt < 8; nt++) {
                    op[(nt * 8 + oc0 + 0) * 8836] = acc[mt][nt][hf * 2 + 0];
                    op[(nt * 8 + oc0 + 1) * 8836] = acc[mt][nt][hf * 2 + 1];
                }
            }
        }
    }
}

// ---------------------------------------------------------------------------
extern "C" void kernel_launch(void* const* d_in, const int* in_sizes, int n_in,
                              void* d_out, int out_size) {
    const float* emb = (const float*)d_in[0];
    const float* x   = (const float*)d_in[1];
    const float* w1w = (const float*)d_in[2];
    const float* w1b = (const float*)d_in[3];
    const float* w2w = (const float*)d_in[4];
    const float* w2b = (const float*)d_in[5];
    float* out = (float*)d_out;

    cudaFuncSetAttribute(convk, cudaFuncAttributeMaxDynamicSharedMemorySize, SMEM_REQ);

    hyper1<<<256, 512>>>(emb, w1w, w1b);
    hyper2<<<WFLAT / 32, 128>>>(w2w, w2b);
    // tile 71 (px >= 9088) is entirely h >= 94 -> dropped
    convk<<<dim3(71, 32), 128, SMEM_REQ>>>(x, out);
}